// round 17
// baseline (speedup 1.0000x reference)
#include <cuda_runtime.h>
#include <cuda_bf16.h>

#define NQ  4
#define NL  5
#define DIM 16
#define NGATES (NL * NQ)

// Circuit unitary, built once by build kernel: U[i][j] packed (re, im).
__device__ unsigned long long g_U[DIM * DIM];

// ---------------------------------------------------------------------------
// Build kernel: ONE block of 256 threads.
// Phase A (60 threads): sincos of the 60 gate angles -> shared.
// Phase B (all threads): propagate the 16 basis columns through the circuit
//   via warp shuffles (each warp handles 2 columns). Writes g_U.
// ---------------------------------------------------------------------------
__global__ __launch_bounds__(256) void build_kernel(const float* __restrict__ w)
{
    __shared__ float2 raw[NGATES][3];              // (sin, cos) per angle

    const int tid = threadIdx.x;

    if (tid < NGATES * 3) {
        int g = tid / 3, k = tid - 3 * g;
        float phi = w[g * 3 + 0], th = w[g * 3 + 1], om = w[g * 3 + 2];
        float ang = (k == 0) ? -0.5f * (phi + om)
                  : (k == 1) ?  0.5f * (phi - om)
                             :  0.5f * th;
        float s, c;
        sincosf(ang, &s, &c);
        raw[g][k] = make_float2(s, c);
    }
    __syncthreads();

    int lane = tid & 31;
    int wrp  = tid >> 5;
    int j = 2 * wrp + (lane >> 4);   // column (basis input state)
    int i = lane & 15;               // amplitude index this thread owns

    float re = (i == j) ? 1.0f : 0.0f;
    float im = 0.0f;

    #pragma unroll
    for (int l = 0; l < NL; l++) {
        #pragma unroll
        for (int q = 0; q < NQ; q++) {
            int g = l * NQ + q;
            float2 P = raw[g][0];    // (sp, cp): e^{-i(phi+om)/2}
            float2 M = raw[g][1];    // (sm, cm): e^{+i(phi-om)/2}
            float2 T = raw[g][2];    // (st, ct): theta/2
            int stride = 8 >> q;     // qubit q lives at bit (3-q)
            bool hi = (i & stride) != 0;
            // self coeff: hi ? U11 : U00 ; partner coeff: hi ? U10 : U01
            float csx = P.y * T.y;
            float csy = (hi ? -P.x : P.x) * T.y;
            float cpx = (hi ?  M.y : -M.y) * T.x;
            float cpy = -M.x * T.x;
            float pre = __shfl_xor_sync(0xffffffffu, re, stride);
            float pim = __shfl_xor_sync(0xffffffffu, im, stride);
            float nre = csx * re - csy * im + cpx * pre - cpy * pim;
            float nim = csx * im + csy * re + cpx * pim + cpy * pre;
            re = nre; im = nim;
        }
        // Entangler: CNOT(q, (q+r)%4) for q=0..3 sequentially; composed:
        // st_new[i] = st_old[s0(s1(s2(s3(i))))]
        int r = (l % (NQ - 1)) + 1;
        int t = i;
        #pragma unroll
        for (int q = NQ - 1; q >= 0; q--) {
            int sc  = 8 >> q;
            int stt = 8 >> ((q + r) & 3);
            t = (t & sc) ? (t ^ stt) : t;
        }
        int src_lane = (lane & 16) | t;
        re = __shfl_sync(0xffffffffu, re, src_lane);
        im = __shfl_sync(0xffffffffu, im, src_lane);
    }

    unsigned long long packed;
    asm("mov.b64 %0, {%1, %2};" : "=l"(packed) : "f"(re), "f"(im));
    g_U[i * DIM + j] = packed;
}

// ---------------------------------------------------------------------------
// Main kernel: one element per thread. Copies the 2KB U from gmem (L2-hot)
// into shared, then Phase C with per-row DUAL f32x2 accumulator chains
// (chain latency halved vs the validated single-chain version); loads stay
// inline in the inner loop (no hoisting -> no spill).
// ---------------------------------------------------------------------------
__global__ __launch_bounds__(256) void qmain_kernel(
    const float4* __restrict__ x, float4* __restrict__ out, int n)
{
    __shared__ unsigned long long sU[DIM * DIM];   // U[i][j] packed (re, im)

    const int tid = threadIdx.x;
    sU[tid] = g_U[tid];                            // 256 entries, 1 per thread
    __syncthreads();

    int b = blockIdx.x * blockDim.x + tid;
    if (b >= n) return;

    float4 xv = x[b];
    float s0, c0, s1, c1, s2, c2, s3, c3;
    __sincosf(0.5f * xv.x, &s0, &c0);
    __sincosf(0.5f * xv.y, &s1, &c1);
    __sincosf(0.5f * xv.z, &s2, &c2);
    __sincosf(0.5f * xv.w, &s3, &c3);

    float a01[4] = {c0 * c1, c0 * s1, s0 * c1, s0 * s1};
    float a23[4] = {c2 * c3, c2 * s3, s2 * c3, s2 * s3};

    // s[j] duplicated into both f32x2 lanes
    unsigned long long sd[DIM];
#pragma unroll
    for (int p = 0; p < 4; p++) {
#pragma unroll
        for (int q = 0; q < 4; q++) {
            float v = a01[p] * a23[q];
            unsigned long long d;
            asm("mov.b64 %0, {%1, %1};" : "=l"(d) : "f"(v));
            sd[p * 4 + q] = d;
        }
    }

    const ulonglong2* sU2 = reinterpret_cast<const ulonglong2*>(sU);

    float prob[DIM];
#pragma unroll
    for (int i = 0; i < DIM; i++) {
        unsigned long long accA = 0ull, accB = 0ull;   // (0.0f, 0.0f) each
#pragma unroll
        for (int jj = 0; jj < 4; jj++) {
            ulonglong2 uA = sU2[i * 8 + jj];        // broadcast LDS.128, inline
            ulonglong2 uB = sU2[i * 8 + 4 + jj];    // broadcast LDS.128, inline
            asm("fma.rn.f32x2 %0, %1, %2, %0;" : "+l"(accA) : "l"(uA.x), "l"(sd[2 * jj    ]));
            asm("fma.rn.f32x2 %0, %1, %2, %0;" : "+l"(accB) : "l"(uB.x), "l"(sd[8 + 2 * jj    ]));
            asm("fma.rn.f32x2 %0, %1, %2, %0;" : "+l"(accA) : "l"(uA.y), "l"(sd[2 * jj + 1]));
            asm("fma.rn.f32x2 %0, %1, %2, %0;" : "+l"(accB) : "l"(uB.y), "l"(sd[8 + 2 * jj + 1]));
        }
        unsigned long long acc;
        asm("add.rn.f32x2 %0, %1, %2;" : "=l"(acc) : "l"(accA), "l"(accB));
        float re, im;
        asm("mov.b64 {%0, %1}, %2;" : "=f"(re), "=f"(im) : "l"(acc));
        prob[i] = re * re + im * im;
    }

    float z0 = 0.f, z1 = 0.f, z2 = 0.f, z3 = 0.f;
#pragma unroll
    for (int i = 0; i < DIM; i++) {
        float pv = prob[i];
        z0 += (i & 8) ? -pv : pv;
        z1 += (i & 4) ? -pv : pv;
        z2 += (i & 2) ? -pv : pv;
        z3 += (i & 1) ? -pv : pv;
    }
    out[b] = make_float4(z0, z1, z2, z3);
}

// ---------------------------------------------------------------------------
extern "C" void kernel_launch(void* const* d_in, const int* in_sizes, int n_in,
                              void* d_out, int out_size)
{
    const float* x;
    const float* w;
    int n;
    // disambiguate inputs by size (weights = 5*4*3 = 60 floats)
    if (in_sizes[0] == NL * NQ * 3) {
        w = (const float*)d_in[0];
        x = (const float*)d_in[1];
        n = in_sizes[1] / 4;
    } else {
        x = (const float*)d_in[0];
        w = (const float*)d_in[1];
        n = in_sizes[0] / 4;
    }

    build_kernel<<<1, 256>>>(w);

    int threads = 256;
    int blocks = (n + threads - 1) / threads;
    qmain_kernel<<<blocks, threads>>>((const float4*)x, (float4*)d_out, n);
}